// round 3
// baseline (speedup 1.0000x reference)
#include <cuda_runtime.h>
#include <cuda_fp16.h>

// OhemMSELoss: loss = w*(p-t)^2 / 2^25 over N=2^25; mean of top-k (k=2^18).
// Pass1: stream inputs -> fp16 unnormalized loss scratch (64 MiB) + 1/8-sampled
//        coarse histogram (replicated global bins).
// Pass2: pick conservative threshold T0 from sample (9-sigma margin).
// Pass3: SIMD-filter scratch (vcmpgeu2); exact 65536-bin histogram of candidates.
// Pass4: suffix-scan 64K bins -> exact top-k sum (fp16 bin pattern == exact value).

#define N_ELEM   33554432
#define NU       (N_ELEM / 8)       // uint4 units of half scratch = 4194304
#define K_KEPT   262144u
#define MARGIN   40960u
#define NSB      4096               // sampled-hist bins  (half bits >> 4)
#define NREP     8                  // replicas to spread hot-bin atomics

static __device__ __half       g_lossh[N_ELEM];        // 64 MiB (fits L2)
static __device__ unsigned     g_shist[NREP][NSB];     // zero-init; self-cleaned by K2
static __device__ unsigned     g_hist64[65536];        // zero-init; self-cleaned by K4
static __device__ unsigned     g_T0;

// ---------------------------------------------------------------- K1: loss + fp16 store + sampled hist
__global__ __launch_bounds__(256) void k_loss(
    const float4* __restrict__ p,
    const float4* __restrict__ t,
    const float4* __restrict__ w)
{
    uint4* out = reinterpret_cast<uint4*>(g_lossh);
    unsigned* hist = g_shist[blockIdx.x & (NREP - 1)];
    const int T = gridDim.x * blockDim.x;

    for (int i = blockIdx.x * blockDim.x + threadIdx.x; i < NU; i += 2 * T) {
        const int j = i + T;
        const bool hj = (j < NU);

        // 12 independent LDG.128 in flight (evict-first: keep L2 for scratch)
        float4 pa = __ldcs(&p[2*i]),   ta = __ldcs(&t[2*i]),   wa = __ldcs(&w[2*i]);
        float4 pb = __ldcs(&p[2*i+1]), tb = __ldcs(&t[2*i+1]), wb = __ldcs(&w[2*i+1]);
        float4 pc, tc, wc, pd, td, wd;
        if (hj) {
            pc = __ldcs(&p[2*j]);   tc = __ldcs(&t[2*j]);   wc = __ldcs(&w[2*j]);
            pd = __ldcs(&p[2*j+1]); td = __ldcs(&t[2*j+1]); wd = __ldcs(&w[2*j+1]);
        }
        {
            float d0 = pa.x-ta.x, d1 = pa.y-ta.y, d2 = pa.z-ta.z, d3 = pa.w-ta.w;
            float d4 = pb.x-tb.x, d5 = pb.y-tb.y, d6 = pb.z-tb.z, d7 = pb.w-tb.w;
            __half2 h0 = __floats2half2_rn(wa.x*d0*d0, wa.y*d1*d1);
            __half2 h1 = __floats2half2_rn(wa.z*d2*d2, wa.w*d3*d3);
            __half2 h2 = __floats2half2_rn(wb.x*d4*d4, wb.y*d5*d5);
            __half2 h3 = __floats2half2_rn(wb.z*d6*d6, wb.w*d7*d7);
            uint4 o;
            o.x = *reinterpret_cast<unsigned*>(&h0);
            o.y = *reinterpret_cast<unsigned*>(&h1);
            o.z = *reinterpret_cast<unsigned*>(&h2);
            o.w = *reinterpret_cast<unsigned*>(&h3);
            out[i] = o;
            if ((i & 7) == 0) atomicAdd(&hist[(o.x & 0xFFFFu) >> 4], 1u);  // 1/64 element sample
        }
        if (hj) {
            float d0 = pc.x-tc.x, d1 = pc.y-tc.y, d2 = pc.z-tc.z, d3 = pc.w-tc.w;
            float d4 = pd.x-td.x, d5 = pd.y-td.y, d6 = pd.z-td.z, d7 = pd.w-td.w;
            __half2 h0 = __floats2half2_rn(wc.x*d0*d0, wc.y*d1*d1);
            __half2 h1 = __floats2half2_rn(wc.z*d2*d2, wc.w*d3*d3);
            __half2 h2 = __floats2half2_rn(wd.x*d4*d4, wd.y*d5*d5);
            __half2 h3 = __floats2half2_rn(wd.z*d6*d6, wd.w*d7*d7);
            uint4 o;
            o.x = *reinterpret_cast<unsigned*>(&h0);
            o.y = *reinterpret_cast<unsigned*>(&h1);
            o.z = *reinterpret_cast<unsigned*>(&h2);
            o.w = *reinterpret_cast<unsigned*>(&h3);
            out[j] = o;
            if ((j & 7) == 0) atomicAdd(&hist[(o.x & 0xFFFFu) >> 4], 1u);
        }
    }
}

// ---------------------------------------------------------------- K2: conservative threshold from sample
__global__ __launch_bounds__(1024) void k_select() {
    __shared__ unsigned ssum[1024];
    const int t = threadIdx.x;

    // merge replicas for my 4 bins, then self-clean for the next graph replay
    unsigned b0 = 0, b1 = 0, b2 = 0, b3 = 0;
    #pragma unroll
    for (int r = 0; r < NREP; r++) {
        uint4 v = reinterpret_cast<const uint4*>(g_shist[r])[t];
        b0 += v.x; b1 += v.y; b2 += v.z; b3 += v.w;
    }
    #pragma unroll
    for (int r = 0; r < NREP; r++)
        reinterpret_cast<uint4*>(g_shist[r])[t] = make_uint4(0, 0, 0, 0);

    ssum[t] = b0 + b1 + b2 + b3;
    __syncthreads();
    // suffix scan (inclusive, from high bins down)
    for (int d = 1; d < 1024; d <<= 1) {
        unsigned v = ssum[t];
        if (t + d < 1024) v += ssum[t + d];
        __syncthreads();
        ssum[t] = v;
        __syncthreads();
    }
    const unsigned TGT = (K_KEPT + MARGIN + 63u) / 64u;   // sampled-count target
    unsigned sufnext = (t < 1023) ? ssum[t + 1] : 0u;
    if (ssum[t] >= TGT && sufnext < TGT) {
        unsigned bins[4] = {b0, b1, b2, b3};
        unsigned cum = sufnext;
        unsigned T0 = 0;
        for (int b = 3; b >= 0; b--) {
            cum += bins[b];
            if (cum >= TGT) { T0 = ((unsigned)(t * 4 + b)) << 4; break; }
        }
        g_T0 = T0;
    }
}

// ---------------------------------------------------------------- K3: SIMD filter + exact 64K hist of candidates
__global__ __launch_bounds__(256) void k_scan() {
    const unsigned T0 = g_T0;
    const unsigned TT = T0 | (T0 << 16);
    const uint4* in = reinterpret_cast<const uint4*>(g_lossh);
    const int T = gridDim.x * blockDim.x;

    #define PROC_UNIT(v) do {                                                   \
        unsigned _m = __vcmpgeu2((v).x, TT) | __vcmpgeu2((v).y, TT)             \
                    | __vcmpgeu2((v).z, TT) | __vcmpgeu2((v).w, TT);            \
        if (_m) {                                                               \
            unsigned _h;                                                        \
            _h = (v).x & 0xFFFFu; if (_h >= T0) atomicAdd(&g_hist64[_h], 1u);   \
            _h = (v).x >> 16;     if (_h >= T0) atomicAdd(&g_hist64[_h], 1u);   \
            _h = (v).y & 0xFFFFu; if (_h >= T0) atomicAdd(&g_hist64[_h], 1u);   \
            _h = (v).y >> 16;     if (_h >= T0) atomicAdd(&g_hist64[_h], 1u);   \
            _h = (v).z & 0xFFFFu; if (_h >= T0) atomicAdd(&g_hist64[_h], 1u);   \
            _h = (v).z >> 16;     if (_h >= T0) atomicAdd(&g_hist64[_h], 1u);   \
            _h = (v).w & 0xFFFFu; if (_h >= T0) atomicAdd(&g_hist64[_h], 1u);   \
            _h = (v).w >> 16;     if (_h >= T0) atomicAdd(&g_hist64[_h], 1u);   \
        }                                                                       \
    } while (0)

    for (int i0 = blockIdx.x * blockDim.x + threadIdx.x; i0 < NU; i0 += 4 * T) {
        const int i1 = i0 + T, i2 = i0 + 2 * T, i3 = i0 + 3 * T;
        uint4 v0 = in[i0];
        const bool h1 = i1 < NU, h2 = i2 < NU, h3 = i3 < NU;
        uint4 v1, v2, v3;
        if (h1) v1 = in[i1];
        if (h2) v2 = in[i2];
        if (h3) v3 = in[i3];
        PROC_UNIT(v0);
        if (h1) PROC_UNIT(v1);
        if (h2) PROC_UNIT(v2);
        if (h3) PROC_UNIT(v3);
    }
    #undef PROC_UNIT
}

// ---------------------------------------------------------------- K4: exact top-k sum from 64K-bin hist
__global__ __launch_bounds__(1024) void k_final(float* __restrict__ out) {
    __shared__ unsigned sc[1024];
    __shared__ double   sw[1024];
    const int t = threadIdx.x;
    const int base = t * 64;

    unsigned cnt = 0; double ws = 0.0;
    #pragma unroll
    for (int jj = 0; jj < 16; jj++) {
        uint4 v = reinterpret_cast<const uint4*>(g_hist64)[t * 16 + jj];
        int b = base + jj * 4;
        if (v.x) { cnt += v.x; ws += (double)v.x * (double)__half2float(__ushort_as_half((unsigned short)(b + 0))); }
        if (v.y) { cnt += v.y; ws += (double)v.y * (double)__half2float(__ushort_as_half((unsigned short)(b + 1))); }
        if (v.z) { cnt += v.z; ws += (double)v.z * (double)__half2float(__ushort_as_half((unsigned short)(b + 2))); }
        if (v.w) { cnt += v.w; ws += (double)v.w * (double)__half2float(__ushort_as_half((unsigned short)(b + 3))); }
    }
    sc[t] = cnt; sw[t] = ws;
    __syncthreads();
    // joint suffix scan (count + weighted sum)
    for (int d = 1; d < 1024; d <<= 1) {
        unsigned c = sc[t]; double x = sw[t];
        if (t + d < 1024) { c += sc[t + d]; x += sw[t + d]; }
        __syncthreads();
        sc[t] = c; sw[t] = x;
        __syncthreads();
    }
    const unsigned cn = (t < 1023) ? sc[t + 1] : 0u;
    const double   wn = (t < 1023) ? sw[t + 1] : 0.0;

    if (sc[t] >= K_KEPT && cn < K_KEPT) {         // unique boundary-owner thread
        unsigned r = K_KEPT - cn;
        double acc = wn;
        for (int b = 63; b >= 0 && r > 0; b--) {
            unsigned c = g_hist64[base + b];      // L2-hot re-read
            if (c) {
                unsigned take = (c < r) ? c : r;
                acc += (double)take * (double)__half2float(__ushort_as_half((unsigned short)(base + b)));
                r -= take;
            }
        }
        out[0] = (float)(acc / 8796093022208.0);  // / (2^25 * 2^18)
    }
    if (t == 0 && sc[0] < K_KEPT) {               // margin failure (9-sigma; ~never)
        double acc = sw[0];
        unsigned r = K_KEPT - sc[0];
        acc += (double)r * (double)__half2float(__ushort_as_half((unsigned short)g_T0));
        out[0] = (float)(acc / 8796093022208.0);
    }
    __syncthreads();
    // self-clean g_hist64 for the next graph replay
    uint4 z = make_uint4(0, 0, 0, 0);
    #pragma unroll
    for (int jj = 0; jj < 16; jj++)
        reinterpret_cast<uint4*>(g_hist64)[t * 16 + jj] = z;
}

// ---------------------------------------------------------------- launch
extern "C" void kernel_launch(void* const* d_in, const int* in_sizes, int n_in,
                              void* d_out, int out_size) {
    const float4* p = (const float4*)d_in[0];   // predict
    const float4* t = (const float4*)d_in[1];   // target
    const float4* w = (const float4*)d_in[2];   // weight
    float* out = (float*)d_out;

    k_loss  <<<1184, 256>>>(p, t, w);
    k_select<<<1, 1024>>>();
    k_scan  <<<1184, 256>>>();
    k_final <<<1, 1024>>>(out);
}

// round 4
// speedup vs baseline: 1.5183x; 1.5183x over previous
#include <cuda_runtime.h>
#include <cuda_fp16.h>

// OhemMSELoss: loss = w*(p-t)^2 / 2^25 over N=2^25; mean of top-k (k=2^18).
// K1: stream inputs -> fp16 unnormalized loss scratch (64 MiB, L2-resident) +
//     1/64-sampled coarse histogram (replicated global bins).
// K2: conservative threshold T0 from sample (~9-sigma margin).
// K3: SIMD-filter scratch (vcmpgeu2); exact 65536-bin histogram of candidates.
// K4a: parallel reduce 64K bins -> 256 coarse (cnt, wsum) pairs.
// K4b: suffix-scan coarse, drill into boundary chunk -> exact top-k mean.
// K5: parallel cleanup of the 64K-bin histogram.

#define N_ELEM   33554432
#define NU       (N_ELEM / 8)       // uint4 units of half scratch = 4194304
#define K_KEPT   262144u
#define MARGIN   40960u
#define NSB      4096               // sampled-hist bins  (half bits >> 4)
#define NREP     8                  // replicas to spread hot-bin atomics

static __device__ __half       g_lossh[N_ELEM];        // 64 MiB (fits L2)
static __device__ unsigned     g_shist[NREP][NSB];     // zero-init; self-cleaned by K2
static __device__ unsigned     g_hist64[65536];        // zero-init; cleaned by K5
static __device__ unsigned     g_T0;
static __device__ unsigned     g_ccnt[256];            // overwritten each run
static __device__ double       g_cwt[256];

__device__ __forceinline__ double bin_val(int b) {
    return (double)__half2float(__ushort_as_half((unsigned short)b));
}

// ---------------------------------------------------------------- K1: loss + fp16 store + sampled hist
__global__ __launch_bounds__(256) void k_loss(
    const float4* __restrict__ p,
    const float4* __restrict__ t,
    const float4* __restrict__ w)
{
    uint4* out = reinterpret_cast<uint4*>(g_lossh);
    unsigned* hist = g_shist[blockIdx.x & (NREP - 1)];
    const int T = gridDim.x * blockDim.x;

    for (int i = blockIdx.x * blockDim.x + threadIdx.x; i < NU; i += 2 * T) {
        const int j = i + T;
        const bool hj = (j < NU);

        // 12 independent LDG.128 in flight (evict-first: keep L2 for scratch)
        float4 pa = __ldcs(&p[2*i]),   ta = __ldcs(&t[2*i]),   wa = __ldcs(&w[2*i]);
        float4 pb = __ldcs(&p[2*i+1]), tb = __ldcs(&t[2*i+1]), wb = __ldcs(&w[2*i+1]);
        float4 pc, tc, wc, pd, td, wd;
        if (hj) {
            pc = __ldcs(&p[2*j]);   tc = __ldcs(&t[2*j]);   wc = __ldcs(&w[2*j]);
            pd = __ldcs(&p[2*j+1]); td = __ldcs(&t[2*j+1]); wd = __ldcs(&w[2*j+1]);
        }
        {
            float d0 = pa.x-ta.x, d1 = pa.y-ta.y, d2 = pa.z-ta.z, d3 = pa.w-ta.w;
            float d4 = pb.x-tb.x, d5 = pb.y-tb.y, d6 = pb.z-tb.z, d7 = pb.w-tb.w;
            __half2 h0 = __floats2half2_rn(wa.x*d0*d0, wa.y*d1*d1);
            __half2 h1 = __floats2half2_rn(wa.z*d2*d2, wa.w*d3*d3);
            __half2 h2 = __floats2half2_rn(wb.x*d4*d4, wb.y*d5*d5);
            __half2 h3 = __floats2half2_rn(wb.z*d6*d6, wb.w*d7*d7);
            uint4 o;
            o.x = *reinterpret_cast<unsigned*>(&h0);
            o.y = *reinterpret_cast<unsigned*>(&h1);
            o.z = *reinterpret_cast<unsigned*>(&h2);
            o.w = *reinterpret_cast<unsigned*>(&h3);
            out[i] = o;
            if ((i & 7) == 0) atomicAdd(&hist[(o.x & 0xFFFFu) >> 4], 1u);  // 1/64 sample
        }
        if (hj) {
            float d0 = pc.x-tc.x, d1 = pc.y-tc.y, d2 = pc.z-tc.z, d3 = pc.w-tc.w;
            float d4 = pd.x-td.x, d5 = pd.y-td.y, d6 = pd.z-td.z, d7 = pd.w-td.w;
            __half2 h0 = __floats2half2_rn(wc.x*d0*d0, wc.y*d1*d1);
            __half2 h1 = __floats2half2_rn(wc.z*d2*d2, wc.w*d3*d3);
            __half2 h2 = __floats2half2_rn(wd.x*d4*d4, wd.y*d5*d5);
            __half2 h3 = __floats2half2_rn(wd.z*d6*d6, wd.w*d7*d7);
            uint4 o;
            o.x = *reinterpret_cast<unsigned*>(&h0);
            o.y = *reinterpret_cast<unsigned*>(&h1);
            o.z = *reinterpret_cast<unsigned*>(&h2);
            o.w = *reinterpret_cast<unsigned*>(&h3);
            out[j] = o;
            if ((j & 7) == 0) atomicAdd(&hist[(o.x & 0xFFFFu) >> 4], 1u);
        }
    }
}

// ---------------------------------------------------------------- K2: conservative threshold from sample
__global__ __launch_bounds__(1024) void k_select() {
    __shared__ unsigned ssum[1024];
    const int t = threadIdx.x;

    unsigned b0 = 0, b1 = 0, b2 = 0, b3 = 0;
    #pragma unroll
    for (int r = 0; r < NREP; r++) {
        uint4 v = reinterpret_cast<const uint4*>(g_shist[r])[t];
        b0 += v.x; b1 += v.y; b2 += v.z; b3 += v.w;
    }
    #pragma unroll
    for (int r = 0; r < NREP; r++)
        reinterpret_cast<uint4*>(g_shist[r])[t] = make_uint4(0, 0, 0, 0);

    ssum[t] = b0 + b1 + b2 + b3;
    __syncthreads();
    for (int d = 1; d < 1024; d <<= 1) {
        unsigned v = ssum[t];
        if (t + d < 1024) v += ssum[t + d];
        __syncthreads();
        ssum[t] = v;
        __syncthreads();
    }
    const unsigned TGT = (K_KEPT + MARGIN + 63u) / 64u;   // sampled-count target
    unsigned sufnext = (t < 1023) ? ssum[t + 1] : 0u;
    if (ssum[t] >= TGT && sufnext < TGT) {
        unsigned bins[4] = {b0, b1, b2, b3};
        unsigned cum = sufnext;
        unsigned T0 = 0;
        for (int b = 3; b >= 0; b--) {
            cum += bins[b];
            if (cum >= TGT) { T0 = ((unsigned)(t * 4 + b)) << 4; break; }
        }
        g_T0 = T0;
    }
}

// ---------------------------------------------------------------- K3: SIMD filter + exact 64K hist of candidates
__global__ __launch_bounds__(256) void k_scan() {
    const unsigned T0 = g_T0;
    const unsigned TT = T0 | (T0 << 16);
    const uint4* in = reinterpret_cast<const uint4*>(g_lossh);
    const int T = gridDim.x * blockDim.x;

    #define PROC_UNIT(v) do {                                                   \
        unsigned _m = __vcmpgeu2((v).x, TT) | __vcmpgeu2((v).y, TT)             \
                    | __vcmpgeu2((v).z, TT) | __vcmpgeu2((v).w, TT);            \
        if (_m) {                                                               \
            unsigned _h;                                                        \
            _h = (v).x & 0xFFFFu; if (_h >= T0) atomicAdd(&g_hist64[_h], 1u);   \
            _h = (v).x >> 16;     if (_h >= T0) atomicAdd(&g_hist64[_h], 1u);   \
            _h = (v).y & 0xFFFFu; if (_h >= T0) atomicAdd(&g_hist64[_h], 1u);   \
            _h = (v).y >> 16;     if (_h >= T0) atomicAdd(&g_hist64[_h], 1u);   \
            _h = (v).z & 0xFFFFu; if (_h >= T0) atomicAdd(&g_hist64[_h], 1u);   \
            _h = (v).z >> 16;     if (_h >= T0) atomicAdd(&g_hist64[_h], 1u);   \
            _h = (v).w & 0xFFFFu; if (_h >= T0) atomicAdd(&g_hist64[_h], 1u);   \
            _h = (v).w >> 16;     if (_h >= T0) atomicAdd(&g_hist64[_h], 1u);   \
        }                                                                       \
    } while (0)

    for (int i0 = blockIdx.x * blockDim.x + threadIdx.x; i0 < NU; i0 += 4 * T) {
        const int i1 = i0 + T, i2 = i0 + 2 * T, i3 = i0 + 3 * T;
        uint4 v0 = in[i0];
        const bool h1 = i1 < NU, h2 = i2 < NU, h3 = i3 < NU;
        uint4 v1, v2, v3;
        if (h1) v1 = in[i1];
        if (h2) v2 = in[i2];
        if (h3) v3 = in[i3];
        PROC_UNIT(v0);
        if (h1) PROC_UNIT(v1);
        if (h2) PROC_UNIT(v2);
        if (h3) PROC_UNIT(v3);
    }
    #undef PROC_UNIT
}

// ---------------------------------------------------------------- K4a: 64K bins -> 256 coarse pairs (parallel)
__global__ __launch_bounds__(256) void k_coarse() {
    __shared__ unsigned swc[8];
    __shared__ double   sww[8];
    const int bin = blockIdx.x * 256 + threadIdx.x;
    unsigned c = g_hist64[bin];
    double   v = c ? (double)c * bin_val(bin) : 0.0;

    #pragma unroll
    for (int o = 16; o; o >>= 1) {
        c += __shfl_down_sync(0xffffffffu, c, o);
        v += __shfl_down_sync(0xffffffffu, v, o);
    }
    if ((threadIdx.x & 31) == 0) { swc[threadIdx.x >> 5] = c; sww[threadIdx.x >> 5] = v; }
    __syncthreads();
    if (threadIdx.x < 8) {
        unsigned cc = swc[threadIdx.x];
        double   vv = sww[threadIdx.x];
        #pragma unroll
        for (int o = 4; o; o >>= 1) {
            cc += __shfl_down_sync(0xffu, cc, o);
            vv += __shfl_down_sync(0xffu, vv, o);
        }
        if (threadIdx.x == 0) { g_ccnt[blockIdx.x] = cc; g_cwt[blockIdx.x] = vv; }
    }
}

// ---------------------------------------------------------------- K4b: finalize (tiny)
__global__ __launch_bounds__(256) void k_final(float* __restrict__ out) {
    __shared__ unsigned sc[256];
    __shared__ double   sw[256];
    __shared__ int      s_chunk;
    __shared__ unsigned s_above_c;
    __shared__ double   s_above_w;
    const int t = threadIdx.x;

    sc[t] = g_ccnt[t];
    sw[t] = g_cwt[t];
    __syncthreads();
    for (int d = 1; d < 256; d <<= 1) {
        unsigned c = sc[t]; double x = sw[t];
        if (t + d < 256) { c += sc[t + d]; x += sw[t + d]; }
        __syncthreads();
        sc[t] = c; sw[t] = x;
        __syncthreads();
    }
    unsigned cn = (t < 255) ? sc[t + 1] : 0u;
    double   wn = (t < 255) ? sw[t + 1] : 0.0;
    if (t == 0) s_chunk = -1;
    __syncthreads();
    if (sc[t] >= K_KEPT && cn < K_KEPT) {
        s_chunk = t; s_above_c = cn; s_above_w = wn;
    }
    __syncthreads();

    if (s_chunk < 0) {                              // margin failure (~9-sigma; ~never)
        if (t == 0) {
            double acc = sw[0] + (double)(K_KEPT - sc[0]) * bin_val((int)g_T0);
            out[0] = (float)(acc / 8796093022208.0);
        }
        return;
    }

    // drill into boundary chunk: 256 bins, cooperative
    const int chunk = s_chunk;
    __syncthreads();
    unsigned c = g_hist64[chunk * 256 + t];
    double   v = c ? (double)c * bin_val(chunk * 256 + t) : 0.0;
    sc[t] = c; sw[t] = v;
    __syncthreads();
    for (int d = 1; d < 256; d <<= 1) {
        unsigned cc = sc[t]; double xx = sw[t];
        if (t + d < 256) { cc += sc[t + d]; xx += sw[t + d]; }
        __syncthreads();
        sc[t] = cc; sw[t] = xx;
        __syncthreads();
    }
    unsigned bn = (t < 255) ? sc[t + 1] : 0u;       // strictly-above within chunk
    double   bw = (t < 255) ? sw[t + 1] : 0.0;
    unsigned above = s_above_c + bn;
    if (s_above_c + sc[t] >= K_KEPT && above < K_KEPT) {
        unsigned r = K_KEPT - above;                // taken from boundary bin
        double acc = s_above_w + bw + (double)r * bin_val(chunk * 256 + t);
        out[0] = (float)(acc / 8796093022208.0);    // / (2^25 * 2^18)
    }
}

// ---------------------------------------------------------------- K5: parallel cleanup of g_hist64
__global__ __launch_bounds__(256) void k_clean() {
    int i = blockIdx.x * blockDim.x + threadIdx.x;   // 64*256 = 16384 uint4
    reinterpret_cast<uint4*>(g_hist64)[i] = make_uint4(0, 0, 0, 0);
}

// ---------------------------------------------------------------- launch
extern "C" void kernel_launch(void* const* d_in, const int* in_sizes, int n_in,
                              void* d_out, int out_size) {
    const float4* p = (const float4*)d_in[0];   // predict
    const float4* t = (const float4*)d_in[1];   // target
    const float4* w = (const float4*)d_in[2];   // weight
    float* out = (float*)d_out;

    k_loss  <<<1184, 256>>>(p, t, w);
    k_select<<<1, 1024>>>();
    k_scan  <<<1184, 256>>>();
    k_coarse<<<256, 256>>>();
    k_final <<<1, 256>>>(out);
    k_clean <<<64, 256>>>();
}